// round 1
// baseline (speedup 1.0000x reference)
#include <cuda_runtime.h>
#include <cuda_bf16.h>

// CopyMechanism: pointer-generator gate + vocab scale + scatter-add.
// B=16, T=128, H=512, V=32000, S=400. One CTA per (b,t) row.
//
// Inputs (metadata order):
//  0 context_vecs [B,T,H] f32
//  1 hidden       [B,T,H] f32
//  2 trg_embs     [B,T,H] f32
//  3 vocab_dists  [B,T,V] f32
//  4 attn_dists   [B,T,S] f32
//  5 src_ids      [B,T,S] i32
//  6 pad_id       (unused by reference math)
//  7 w_h  [1,H] f32
//  8 w_s  [1,H] f32
//  9 w_x_w [1,H] f32
// 10 w_x_b [1]  f32
// output: [B,T,V] f32

#define HDIM 512
#define VDIM 32000
#define SDIM 400
#define NTHREADS 256

__global__ __launch_bounds__(NTHREADS)
void copy_mechanism_kernel(
    const float* __restrict__ ctx,
    const float* __restrict__ hid,
    const float* __restrict__ trg,
    const float* __restrict__ vocab,
    const float* __restrict__ attn,
    const int*   __restrict__ src_ids,
    const float* __restrict__ w_h,
    const float* __restrict__ w_s,
    const float* __restrict__ w_x,
    const float* __restrict__ w_b,
    float* __restrict__ out)
{
    const int row = blockIdx.x;          // 0 .. B*T-1
    const int tid = threadIdx.x;
    const int lane = tid & 31;
    const int warp = tid >> 5;

    __shared__ float s_red[NTHREADS / 32];
    __shared__ float s_pgen;

    // ---- Phase 1: gate logit = <ctx,w_h> + <hid,w_s> + <trg,w_x> + b ----
    // H=512, 256 threads -> 2 elements each; vectorize as float2.
    {
        const float2* c2 = reinterpret_cast<const float2*>(ctx + (size_t)row * HDIM);
        const float2* h2 = reinterpret_cast<const float2*>(hid + (size_t)row * HDIM);
        const float2* t2 = reinterpret_cast<const float2*>(trg + (size_t)row * HDIM);
        const float2* wh2 = reinterpret_cast<const float2*>(w_h);
        const float2* ws2 = reinterpret_cast<const float2*>(w_s);
        const float2* wx2 = reinterpret_cast<const float2*>(w_x);

        // HDIM/2 = 256 float2 -> exactly one per thread
        float2 cv = c2[tid], hv = h2[tid], tv = t2[tid];
        float2 wh = wh2[tid], ws = ws2[tid], wx = wx2[tid];
        float acc = cv.x * wh.x + cv.y * wh.y
                  + hv.x * ws.x + hv.y * ws.y
                  + tv.x * wx.x + tv.y * wx.y;

        // warp reduce
        #pragma unroll
        for (int o = 16; o > 0; o >>= 1)
            acc += __shfl_down_sync(0xFFFFFFFFu, acc, o);
        if (lane == 0) s_red[warp] = acc;
        __syncthreads();
        if (warp == 0) {
            float v = (lane < NTHREADS / 32) ? s_red[lane] : 0.0f;
            #pragma unroll
            for (int o = 4; o > 0; o >>= 1)
                v += __shfl_down_sync(0xFFFFFFFFu, v, o);
            if (lane == 0) {
                float logit = v + w_b[0];
                s_pgen = 1.0f / (1.0f + __expf(-logit));
            }
        }
        __syncthreads();
    }

    const float p_gen = s_pgen;
    const float one_minus = 1.0f - p_gen;

    // ---- Phase 2: out = p_gen * vocab (vectorized float4) ----
    {
        const float4* v4 = reinterpret_cast<const float4*>(vocab + (size_t)row * VDIM);
        float4* o4 = reinterpret_cast<float4*>(out + (size_t)row * VDIM);
        const int n4 = VDIM / 4;  // 8000
        #pragma unroll 4
        for (int i = tid; i < n4; i += NTHREADS) {
            float4 v = v4[i];
            v.x *= p_gen; v.y *= p_gen; v.z *= p_gen; v.w *= p_gen;
            o4[i] = v;
        }
    }

    __syncthreads();  // row fully written before scatter reads-modify-writes it

    // ---- Phase 3: scatter-add (1-p_gen)*attn into this row ----
    {
        const float* a = attn + (size_t)row * SDIM;
        const int* ids = src_ids + (size_t)row * SDIM;
        float* orow = out + (size_t)row * VDIM;
        for (int j = tid; j < SDIM; j += NTHREADS) {
            atomicAdd(&orow[ids[j]], one_minus * a[j]);
        }
    }
}

extern "C" void kernel_launch(void* const* d_in, const int* in_sizes, int n_in,
                              void* d_out, int out_size) {
    const float* ctx   = (const float*)d_in[0];
    const float* hid   = (const float*)d_in[1];
    const float* trg   = (const float*)d_in[2];
    const float* vocab = (const float*)d_in[3];
    const float* attn  = (const float*)d_in[4];
    const int*   sid   = (const int*)d_in[5];
    // d_in[6] = pad_id (unused)
    const float* w_h   = (const float*)d_in[7];
    const float* w_s   = (const float*)d_in[8];
    const float* w_x   = (const float*)d_in[9];
    const float* w_b   = (const float*)d_in[10];
    float* out = (float*)d_out;

    const int rows = in_sizes[0] / HDIM;  // B*T = 2048
    copy_mechanism_kernel<<<rows, NTHREADS>>>(
        ctx, hid, trg, vocab, attn, sid, w_h, w_s, w_x, w_b, out);
}